// round 5
// baseline (speedup 1.0000x reference)
#include <cuda_runtime.h>
#include <math.h>

#define B_  32
#define L_  64
#define D_  768
#define LL_ (L_*L_)     // 4096
#define OUTD_ (2*D_)    // 1536

// stageB1 tiling
#define OT_  128        // outputs per block
#define KC_  32         // k per chunk
#define KS_  24         // 768 / 32 k-chunks

// scratch
__device__ float g_pooled[B_ * D_];
__device__ float g_t[B_ * 2 * L_];        // t1 (64) then t2 (64) per batch
__device__ float g_ca[B_ * L_];           // coefficient for a1 row r (0 if unused)
__device__ float g_cb[B_ * L_];           // NEGATED coefficient for a2 row r
__device__ float g_part[KS_ * B_ * OUTD_];// split-k partials (4.7 MB)

// ---------------------------------------------------------------------------
// T: t[b, r] = dot(row, we_w). grid = (16, B_), block = 256. Warp per row.
// ---------------------------------------------------------------------------
__global__ __launch_bounds__(256) void stageT(
    const float* __restrict__ a1, const float* __restrict__ a2,
    const float* __restrict__ we_w)
{
    __shared__ float sw[D_];
    const int b    = blockIdx.y;
    const int lane = threadIdx.x & 31;
    const int wid  = threadIdx.x >> 5;
    const int task = blockIdx.x * 8 + wid;   // 0..127

    for (int i = threadIdx.x; i < D_; i += 256) sw[i] = we_w[i];
    __syncthreads();

    const float4* row = (task < L_)
        ? ((const float4*)(a1 + (size_t)b * L_ * D_) + task * (D_/4))
        : ((const float4*)(a2 + (size_t)b * L_ * D_) + (task - L_) * (D_/4));
    const float4* swv = (const float4*)sw;

    float s = 0.f;
    #pragma unroll
    for (int k = 0; k < 6; k++) {
        float4 v = row[lane + 32*k];
        float4 w = swv[lane + 32*k];
        s += v.x*w.x + v.y*w.y + v.z*w.z + v.w*w.w;
    }
    #pragma unroll
    for (int o = 16; o; o >>= 1) s += __shfl_xor_sync(0xffffffffu, s, o);
    if (lane == 0) g_t[b * 2*L_ + task] = s;
}

// ---------------------------------------------------------------------------
// M: per-batch masked-softmax marginals from t-values. grid = B_, block 256.
// ---------------------------------------------------------------------------
__global__ __launch_bounds__(256) void stageM(
    const int* __restrict__ m1, const int* __restrict__ m2)
{
    __shared__ float t1[L_], t2[L_];
    __shared__ float rows[L_], cols[L_];
    __shared__ float red[8];
    __shared__ int   sl1, sl2;
    __shared__ float smax, sinvd;

    const int b    = blockIdx.x;
    const int tid  = threadIdx.x;
    const int lane = tid & 31;
    const int wid  = tid >> 5;

    if (tid < 2*L_) {
        float v = g_t[b*2*L_ + tid];
        if (tid < L_) t1[tid] = v; else t2[tid - L_] = v;
    }
    if (tid < L_) { rows[tid] = 0.f; cols[tid] = 0.f; }

    if (wid == 0) {
        int s = m1[b*L_ + lane] + m1[b*L_ + lane + 32];
        #pragma unroll
        for (int o = 16; o; o >>= 1) s += __shfl_xor_sync(0xffffffffu, s, o);
        if (lane == 0) sl1 = s - 2;
    } else if (wid == 1) {
        int s = m2[b*L_ + lane] + m2[b*L_ + lane + 32];
        #pragma unroll
        for (int o = 16; o; o >>= 1) s += __shfl_xor_sync(0xffffffffu, s, o);
        if (lane == 0) sl2 = s - 2;
    }
    __syncthreads();

    const int l1 = sl1, l2 = sl2;

    float lmax = -1e7f;
    for (int i = wid; i < l1; i += 8) {
        const float ti = t1[i+1];
        #pragma unroll
        for (int base = 0; base < L_; base += 32) {
            int j = base + lane;
            if (j < l2) {
                float we = ti - t2[j+1];
                float m = (fabsf(we) < 1e-7f) ? -1e7f : we;
                lmax = fmaxf(lmax, m);
            }
        }
    }
    #pragma unroll
    for (int o = 16; o; o >>= 1) lmax = fmaxf(lmax, __shfl_xor_sync(0xffffffffu, lmax, o));
    if (lane == 0) red[wid] = lmax;
    __syncthreads();
    if (tid == 0) {
        float m = red[0];
        #pragma unroll
        for (int i = 1; i < 8; i++) m = fmaxf(m, red[i]);
        smax = m;
    }
    __syncthreads();
    const float mx = smax;

    for (int i = wid; i < l1; i += 8) {
        const float ti = t1[i+1];
        float s = 0.f;
        #pragma unroll
        for (int base = 0; base < L_; base += 32) {
            int j = base + lane;
            if (j < l2) {
                float we = ti - t2[j+1];
                float m = (fabsf(we) < 1e-7f) ? -1e7f : we;
                s += __expf(m - mx);
            }
        }
        #pragma unroll
        for (int o = 16; o; o >>= 1) s += __shfl_xor_sync(0xffffffffu, s, o);
        if (lane == 0) rows[i] = s;
    }
    for (int j = wid; j < l2; j += 8) {
        const float tj = t2[j+1];
        float s = 0.f;
        #pragma unroll
        for (int base = 0; base < L_; base += 32) {
            int i = base + lane;
            if (i < l1) {
                float we = t1[i+1] - tj;
                float m = (fabsf(we) < 1e-7f) ? -1e7f : we;
                s += __expf(m - mx);
            }
        }
        #pragma unroll
        for (int o = 16; o; o >>= 1) s += __shfl_xor_sync(0xffffffffu, s, o);
        if (lane == 0) cols[j] = s;
    }
    __syncthreads();

    if (wid == 0) {
        float s = rows[lane] + rows[lane + 32];
        #pragma unroll
        for (int o = 16; o; o >>= 1) s += __shfl_xor_sync(0xffffffffu, s, o);
        if (lane == 0) {
            float pad = (float)(LL_ - l1*l2) * __expf(-1e7f - mx);
            sinvd = 1.f / (s + pad);
        }
    }
    __syncthreads();
    const float invd = sinvd;

    if (tid < L_) {
        float v = (tid >= 1 && tid - 1 < l1) ? rows[tid-1] * invd : 0.f;
        g_ca[b*L_ + tid] = v;
    } else if (tid < 2*L_) {
        int j = tid - L_;
        float v = (j >= 1 && j - 1 < l2) ? -cols[j-1] * invd : 0.f;
        g_cb[b*L_ + j] = v;
    }
}

// ---------------------------------------------------------------------------
// A2: pooled[b,:] = sum_r ca[r]*a1[b,r,:] + cb[r]*a2[b,r,:]
// grid = (6, B_), block = 256.
// ---------------------------------------------------------------------------
__global__ __launch_bounds__(256) void stageA2(
    const float* __restrict__ a1, const float* __restrict__ a2)
{
    __shared__ float4 part[8][32];

    const int b    = blockIdx.y;
    const int cc   = blockIdx.x;
    const int lane = threadIdx.x & 31;
    const int rg   = threadIdx.x >> 5;
    const int col  = cc*32 + lane;

    const float4* base1v = (const float4*)(a1 + (size_t)b * L_ * D_);
    const float4* base2v = (const float4*)(a2 + (size_t)b * L_ * D_);
    const float*  ca = g_ca + b*L_;
    const float*  cb = g_cb + b*L_;

    float4 acc = make_float4(0.f, 0.f, 0.f, 0.f);
    #pragma unroll
    for (int k = 0; k < 8; k++) {
        const int r = rg + 8*k;
        const float c1 = ca[r];
        const float c2 = cb[r];
        float4 v1 = base1v[r*(D_/4) + col];
        float4 v2 = base2v[r*(D_/4) + col];
        acc.x += c1*v1.x + c2*v2.x;
        acc.y += c1*v1.y + c2*v2.y;
        acc.z += c1*v1.z + c2*v2.z;
        acc.w += c1*v1.w + c2*v2.w;
    }
    part[rg][lane] = acc;
    __syncthreads();

    if (threadIdx.x < 32) {
        float4 s = part[0][lane];
        #pragma unroll
        for (int k = 1; k < 8; k++) {
            float4 v = part[k][lane];
            s.x += v.x; s.y += v.y; s.z += v.z; s.w += v.w;
        }
        ((float4*)g_pooled)[b*(D_/4) + col] = s;
    }
}

// ---------------------------------------------------------------------------
// B1: split-k GEMM partials. part[kc][b][o] = sum_{k in chunk} pooled[b][k]*fc_w[o][k]
// grid = (12 o-tiles, 24 k-chunks), block = 256. Thread: 4b x 4o micro-tile.
// ---------------------------------------------------------------------------
__global__ __launch_bounds__(256) void stageB1(const float* __restrict__ fc_w)
{
    __shared__ float4 w_s[8 * 132];   // [kq][o] padded (132) against bank conflicts
    __shared__ float4 p_s[8 * 32];    // [kq][b]

    const int tid = threadIdx.x;
    const int o0  = blockIdx.x * OT_;          // 0..1408 step 128
    const int kc  = blockIdx.y;                // 0..23
    const int k4  = kc * (KC_/4);              // float4 k offset

    // stage w tile: 128 o x 8 kq float4s = 1024, 4 per thread, coalesced reads
    {
        const float4* fw4 = (const float4*)fc_w;
        #pragma unroll
        for (int r = 0; r < 4; r++) {
            int idx = tid + 256*r;             // 0..1023
            int o   = idx >> 3;
            int kq  = idx & 7;
            w_s[kq*132 + o] = fw4[(size_t)(o0 + o)*(D_/4) + k4 + kq];
        }
    }
    // stage p tile: 32 b x 8 kq float4s = 256, 1 per thread
    {
        const float4* pool4 = (const float4*)g_pooled;
        int b  = tid & 31;
        int kq = tid >> 5;
        p_s[kq*32 + b] = pool4[b*(D_/4) + k4 + kq];
    }
    __syncthreads();

    const int og = tid & 31;     // o = o0 + og*4 + oi
    const int bg = tid >> 5;     // b = bg*4 + bi

    float acc[4][4];
    #pragma unroll
    for (int i = 0; i < 4; i++)
        #pragma unroll
        for (int j = 0; j < 4; j++) acc[i][j] = 0.f;

    #pragma unroll
    for (int kq = 0; kq < 8; kq++) {
        float4 wv[4], pv[4];
        #pragma unroll
        for (int r = 0; r < 4; r++) wv[r] = w_s[kq*132 + og*4 + r];
        #pragma unroll
        for (int r = 0; r < 4; r++) pv[r] = p_s[kq*32 + bg*4 + r];
        #pragma unroll
        for (int bi = 0; bi < 4; bi++)
            #pragma unroll
            for (int oi = 0; oi < 4; oi++)
                acc[bi][oi] += pv[bi].x*wv[oi].x + pv[bi].y*wv[oi].y
                             + pv[bi].z*wv[oi].z + pv[bi].w*wv[oi].w;
    }

    float4* part4 = (float4*)g_part;
    #pragma unroll
    for (int bi = 0; bi < 4; bi++) {
        int b = bg*4 + bi;
        part4[(size_t)(kc*B_ + b)*(OUTD_/4) + (o0/4) + og] =
            make_float4(acc[bi][0], acc[bi][1], acc[bi][2], acc[bi][3]);
    }
}

// ---------------------------------------------------------------------------
// B2: out[b][o] = tanh( sum_s part[s][b][o] + fc_b[o] ). grid = 48 x 256.
// ---------------------------------------------------------------------------
__global__ __launch_bounds__(256) void stageB2(
    const float* __restrict__ fc_b, float* __restrict__ out)
{
    const int gid = blockIdx.x * 256 + threadIdx.x;   // 0..12287 (float4 elems)
    const int b   = gid / (OUTD_/4);
    const int o4  = gid % (OUTD_/4);

    const float4* part4 = (const float4*)g_part;
    float4 s = make_float4(0.f, 0.f, 0.f, 0.f);
    #pragma unroll
    for (int sc = 0; sc < KS_; sc++) {
        float4 v = part4[(size_t)(sc*B_ + b)*(OUTD_/4) + o4];
        s.x += v.x; s.y += v.y; s.z += v.z; s.w += v.w;
    }
    float4 bias = ((const float4*)fc_b)[o4];
    float4 r;
    r.x = tanhf(s.x + bias.x);
    r.y = tanhf(s.y + bias.y);
    r.z = tanhf(s.z + bias.z);
    r.w = tanhf(s.w + bias.w);
    ((float4*)out)[(size_t)b*(OUTD_/4) + o4] = r;
}

extern "C" void kernel_launch(void* const* d_in, const int* in_sizes, int n_in,
                              void* d_out, int out_size)
{
    const float* a1   = (const float*)d_in[0];  // (B, L, D)
    const float* a2   = (const float*)d_in[1];  // (B, L, D)
    const int*   m1   = (const int*)  d_in[2];  // (B, L)
    const int*   m2   = (const int*)  d_in[3];  // (B, L)
    const float* we_w = (const float*)d_in[4];  // (1, D)
    const float* fc_w = (const float*)d_in[5];  // (2D, D)
    const float* fc_b = (const float*)d_in[6];  // (2D,)
    float* out = (float*)d_out;                 // (B, 2D)

    stageT<<<dim3(16, B_), 256>>>(a1, a2, we_w);
    stageM<<<B_, 256>>>(m1, m2);
    stageA2<<<dim3(6, B_), 256>>>(a1, a2);
    stageB1<<<dim3(OUTD_/OT_, KS_), 256>>>(fc_w);
    stageB2<<<48, 256>>>(fc_b, out);
}

// round 6
// speedup vs baseline: 1.1105x; 1.1105x over previous
#include <cuda_runtime.h>
#include <math.h>

#define B_    32
#define L_    64
#define D_    768
#define LL_   (L_*L_)     // 4096
#define OUTD_ (2*D_)      // 1536
#define GRID_ 148
#define NT_   512
#define NW_   16          // warps per block

// scratch (zero-initialized at load; barrier counters never reset -> replay-safe)
__device__ float    g_pooled[B_ * D_];
__device__ float    g_t[B_ * 2 * L_];     // t1 (64) then t2 (64) per batch
__device__ float    g_ca[B_ * L_];        // coefficient for a1 row r (0 if unused)
__device__ float    g_cb[B_ * L_];        // NEGATED coefficient for a2 row r
__device__ unsigned g_bar[4];             // monotonic grid barrier counters

// grid-wide barrier: arrive (release) + spin to next multiple of GRID_ (acquire)
__device__ __forceinline__ void gsync(int i)
{
    __syncthreads();
    if (threadIdx.x == 0) {
        __threadfence();
        unsigned v = atomicAdd(&g_bar[i], 1u) + 1u;
        unsigned target = ((v - 1u) / GRID_ + 1u) * GRID_;
        while (*((volatile unsigned*)&g_bar[i]) < target) __nanosleep(64);
        __threadfence();
    }
    __syncthreads();
}

__global__ __launch_bounds__(NT_, 1) void fused(
    const float* __restrict__ a1, const float* __restrict__ a2,
    const int*   __restrict__ m1, const int*   __restrict__ m2,
    const float* __restrict__ we_w,
    const float* __restrict__ fc_w, const float* __restrict__ fc_b,
    float* __restrict__ out)
{
    __shared__ float  sw[D_];             // 3 KB   (phase T)
    __shared__ float  t1[L_], t2[L_];     //        (phase M)
    __shared__ float  rowsh[L_], colsh[L_];
    __shared__ float  red[NW_];
    __shared__ int    sl1, sl2;
    __shared__ float  smax, sinvd;
    __shared__ float4 partt[NW_][32];     // 8 KB   (phase A2)
    __shared__ float  sB[8 * D_];         // 24 KB  (phase B)

    const int tid  = threadIdx.x;
    const int lane = tid & 31;
    const int wid  = tid >> 5;
    const int bid  = blockIdx.x;

    // ============================ Phase T ===============================
    // t[b, task] = dot(row, we_w); 4096 warp-row tasks chip-wide.
    for (int i = tid; i < D_; i += NT_) sw[i] = we_w[i];
    __syncthreads();

    const float4* swv = (const float4*)sw;
    for (int wt = bid * NW_ + wid; wt < B_ * 2 * L_; wt += GRID_ * NW_) {
        const int b    = wt >> 7;          // /128
        const int task = wt & 127;
        const float4* row = (task < L_)
            ? ((const float4*)(a1 + (size_t)b * L_ * D_) + task * (D_/4))
            : ((const float4*)(a2 + (size_t)b * L_ * D_) + (task - L_) * (D_/4));
        float s = 0.f;
        #pragma unroll
        for (int k = 0; k < 6; k++) {
            float4 v = row[lane + 32*k];
            float4 w = swv[lane + 32*k];
            s += v.x*w.x + v.y*w.y + v.z*w.z + v.w*w.w;
        }
        #pragma unroll
        for (int o = 16; o; o >>= 1) s += __shfl_xor_sync(0xffffffffu, s, o);
        if (lane == 0) g_t[b * 2*L_ + task] = s;
    }
    gsync(0);

    // ============================ Phase M ===============================
    // blocks 0..31: masked-softmax marginals for batch b = bid.
    if (bid < B_) {
        const int b = bid;
        if (tid < 2*L_) {
            float v = g_t[b*2*L_ + tid];
            if (tid < L_) t1[tid] = v; else t2[tid - L_] = v;
        }
        if (tid < L_) { rowsh[tid] = 0.f; colsh[tid] = 0.f; }

        if (wid == 0) {
            int s = m1[b*L_ + lane] + m1[b*L_ + lane + 32];
            #pragma unroll
            for (int o = 16; o; o >>= 1) s += __shfl_xor_sync(0xffffffffu, s, o);
            if (lane == 0) sl1 = s - 2;
        } else if (wid == 1) {
            int s = m2[b*L_ + lane] + m2[b*L_ + lane + 32];
            #pragma unroll
            for (int o = 16; o; o >>= 1) s += __shfl_xor_sync(0xffffffffu, s, o);
            if (lane == 0) sl2 = s - 2;
        }
        __syncthreads();

        const int l1 = sl1, l2 = sl2;

        // max over valid masked logits (padding contributes -1e7 floor)
        float lmax = -1e7f;
        for (int i = wid; i < l1; i += NW_) {
            const float ti = t1[i+1];
            #pragma unroll
            for (int base = 0; base < L_; base += 32) {
                int j = base + lane;
                if (j < l2) {
                    float we = ti - t2[j+1];
                    float m = (fabsf(we) < 1e-7f) ? -1e7f : we;
                    lmax = fmaxf(lmax, m);
                }
            }
        }
        #pragma unroll
        for (int o = 16; o; o >>= 1) lmax = fmaxf(lmax, __shfl_xor_sync(0xffffffffu, lmax, o));
        if (lane == 0) red[wid] = lmax;
        __syncthreads();
        if (tid == 0) {
            float m = red[0];
            #pragma unroll
            for (int i = 1; i < NW_; i++) m = fmaxf(m, red[i]);
            smax = m;
        }
        __syncthreads();
        const float mx = smax;

        for (int i = wid; i < l1; i += NW_) {
            const float ti = t1[i+1];
            float s = 0.f;
            #pragma unroll
            for (int base = 0; base < L_; base += 32) {
                int j = base + lane;
                if (j < l2) {
                    float we = ti - t2[j+1];
                    float m = (fabsf(we) < 1e-7f) ? -1e7f : we;
                    s += __expf(m - mx);
                }
            }
            #pragma unroll
            for (int o = 16; o; o >>= 1) s += __shfl_xor_sync(0xffffffffu, s, o);
            if (lane == 0) rowsh[i] = s;
        }
        for (int j = wid; j < l2; j += NW_) {
            const float tj = t2[j+1];
            float s = 0.f;
            #pragma unroll
            for (int base = 0; base < L_; base += 32) {
                int i = base + lane;
                if (i < l1) {
                    float we = t1[i+1] - tj;
                    float m = (fabsf(we) < 1e-7f) ? -1e7f : we;
                    s += __expf(m - mx);
                }
            }
            #pragma unroll
            for (int o = 16; o; o >>= 1) s += __shfl_xor_sync(0xffffffffu, s, o);
            if (lane == 0) colsh[j] = s;
        }
        __syncthreads();

        if (wid == 0) {
            float s = rowsh[lane] + rowsh[lane + 32];
            #pragma unroll
            for (int o = 16; o; o >>= 1) s += __shfl_xor_sync(0xffffffffu, s, o);
            if (lane == 0) {
                float pad = (float)(LL_ - l1*l2) * __expf(-1e7f - mx);
                sinvd = 1.f / (s + pad);
            }
        }
        __syncthreads();
        const float invd = sinvd;

        if (tid < L_) {
            g_ca[b*L_ + tid] = (tid >= 1 && tid - 1 < l1) ? rowsh[tid-1] * invd : 0.f;
        } else if (tid < 2*L_) {
            int j = tid - L_;
            g_cb[b*L_ + j] = (j >= 1 && j - 1 < l2) ? -colsh[j-1] * invd : 0.f;
        }
    }
    gsync(1);

    // ============================ Phase A2 ==============================
    // pooled[b,:] = sum_r ca[r]*a1[b,r,:] + cb[r]*a2[b,r,:]  (192 tasks)
    for (int t = bid; t < 6 * B_; t += GRID_) {
        const int b   = t / 6;
        const int cc  = t % 6;
        const int col = cc*32 + lane;

        const float4* base1v = (const float4*)(a1 + (size_t)b * L_ * D_);
        const float4* base2v = (const float4*)(a2 + (size_t)b * L_ * D_);
        const float*  ca = g_ca + b*L_;
        const float*  cb = g_cb + b*L_;

        float4 acc = make_float4(0.f, 0.f, 0.f, 0.f);
        #pragma unroll
        for (int k = 0; k < 4; k++) {
            const int r = wid + NW_*k;          // 16 warps x 4 = 64 rows
            const float c1 = ca[r];
            const float c2 = cb[r];
            float4 v1 = base1v[r*(D_/4) + col];
            float4 v2 = base2v[r*(D_/4) + col];
            acc.x += c1*v1.x + c2*v2.x;
            acc.y += c1*v1.y + c2*v2.y;
            acc.z += c1*v1.z + c2*v2.z;
            acc.w += c1*v1.w + c2*v2.w;
        }
        partt[wid][lane] = acc;
        __syncthreads();
        if (tid < 32) {
            float4 s = partt[0][lane];
            #pragma unroll
            for (int k = 1; k < NW_; k++) {
                float4 v = partt[k][lane];
                s.x += v.x; s.y += v.y; s.z += v.z; s.w += v.w;
            }
            ((float4*)g_pooled)[b*(D_/4) + col] = s;
        }
        __syncthreads();
    }
    gsync(2);

    // ============================ Phase B ===============================
    // out[b,o] = tanh(dot(pooled[b], fc_w[o]) + fc_b[o]); 192 8-row tiles.
    // Warp owns 2 batches; pooled hoisted into registers once.
    const int b0 = wid * 2;
    const float4* poolv = (const float4*)g_pooled;
    float4 p[2][6];
    #pragma unroll
    for (int bb = 0; bb < 2; bb++)
        #pragma unroll
        for (int k = 0; k < 6; k++)
            p[bb][k] = poolv[(b0 + bb)*(D_/4) + lane + 32*k];

    for (int t = bid; t < OUTD_/8; t += GRID_) {
        const int o0 = t * 8;
        // stage 8x768 floats = 1536 float4, 3 per thread
        {
            const float4* src = (const float4*)(fc_w + (size_t)o0 * D_);
            float4*       dst = (float4*)sB;
            #pragma unroll
            for (int k = 0; k < 3; k++)
                dst[tid + NT_*k] = src[tid + NT_*k];
        }
        __syncthreads();

        const float4* sBv = (const float4*)sB;
        #pragma unroll
        for (int r = 0; r < 8; r++) {
            const int o = o0 + r;
            float x0 = 0.f, x1 = 0.f;
            #pragma unroll
            for (int k = 0; k < 6; k++) {
                float4 w = sBv[r*(D_/4) + lane + 32*k];
                x0 += w.x*p[0][k].x + w.y*p[0][k].y + w.z*p[0][k].z + w.w*p[0][k].w;
                x1 += w.x*p[1][k].x + w.y*p[1][k].y + w.z*p[1][k].z + w.w*p[1][k].w;
            }
            #pragma unroll
            for (int off = 16; off; off >>= 1) {
                x0 += __shfl_xor_sync(0xffffffffu, x0, off);
                x1 += __shfl_xor_sync(0xffffffffu, x1, off);
            }
            if (lane == 0) {
                const float bias = fc_b[o];
                out[(size_t)(b0+0)*OUTD_ + o] = tanhf(x0 + bias);
                out[(size_t)(b0+1)*OUTD_ + o] = tanhf(x1 + bias);
            }
        }
        __syncthreads();
    }
}

extern "C" void kernel_launch(void* const* d_in, const int* in_sizes, int n_in,
                              void* d_out, int out_size)
{
    const float* a1   = (const float*)d_in[0];  // (B, L, D)
    const float* a2   = (const float*)d_in[1];  // (B, L, D)
    const int*   m1   = (const int*)  d_in[2];  // (B, L)
    const int*   m2   = (const int*)  d_in[3];  // (B, L)
    const float* we_w = (const float*)d_in[4];  // (1, D)
    const float* fc_w = (const float*)d_in[5];  // (2D, D)
    const float* fc_b = (const float*)d_in[6];  // (2D,)
    float* out = (float*)d_out;                 // (B, 2D)

    fused<<<GRID_, NT_>>>(a1, a2, m1, m2, we_w, fc_w, fc_b, out);
}